// round 15
// baseline (speedup 1.0000x reference)
#include <cuda_runtime.h>
#include <cuda_bf16.h>

// Elementwise clamp to [-0.5f, 0.5f] of n fp32 elements.
// Persistent-grid HBM streamer: ONE wave of CTAs (SMs x occupancy), grid-stride
// loop with 4 independent float4 loads per iteration (MLP=4), streaming cache
// hints. Eliminates the ~14 wave transitions of the one-shot launch.

#define LO (-0.5f)
#define HI ( 0.5f)

__device__ __forceinline__ float4 clamp4(float4 v) {
    v.x = fminf(fmaxf(v.x, LO), HI);
    v.y = fminf(fmaxf(v.y, LO), HI);
    v.z = fminf(fmaxf(v.z, LO), HI);
    v.w = fminf(fmaxf(v.w, LO), HI);
    return v;
}

__global__ void __launch_bounds__(256)
clip_persist_kernel(const float4* __restrict__ in, float4* __restrict__ out,
                    unsigned n4) {
    const unsigned gsz = gridDim.x * blockDim.x;        // threads in grid
    const unsigned step = gsz * 4u;                     // float4s per chunk
    unsigned i = blockIdx.x * blockDim.x + threadIdx.x;

    // Full 4-vector chunks: 4 independent 128-bit loads in flight per thread.
    for (; i + 3u * gsz < n4; i += step) {
        float4 v0 = __ldcs(in + i);
        float4 v1 = __ldcs(in + i + gsz);
        float4 v2 = __ldcs(in + i + 2u * gsz);
        float4 v3 = __ldcs(in + i + 3u * gsz);
        __stcs(out + i,            clamp4(v0));
        __stcs(out + i + gsz,      clamp4(v1));
        __stcs(out + i + 2u * gsz, clamp4(v2));
        __stcs(out + i + 3u * gsz, clamp4(v3));
    }
    // Tail vectors.
    for (; i < n4; i += gsz) {
        __stcs(out + i, clamp4(__ldcs(in + i)));
    }
}

// Grid-stride scalar fallback (non-vectorizable sizes / element tail).
__global__ void clip_scalar_kernel(const float* __restrict__ in,
                                   float* __restrict__ out, long long n) {
    long long stride = (long long)gridDim.x * blockDim.x;
    for (long long i = (long long)blockIdx.x * blockDim.x + threadIdx.x; i < n; i += stride) {
        out[i] = fminf(fmaxf(__ldcs(in + i), LO), HI);
    }
}

extern "C" void kernel_launch(void* const* d_in, const int* in_sizes, int n_in,
                              void* d_out, int out_size) {
    const float* x = (const float*)d_in[0];
    float* out = (float*)d_out;
    long long n = (long long)in_sizes[0];

    constexpr int THREADS = 256;

    int sm_count = 148;
    cudaDeviceGetAttribute(&sm_count, cudaDevAttrMultiProcessorCount, 0);

    int blocks_per_sm = 1;
    cudaOccupancyMaxActiveBlocksPerMultiprocessor(
        &blocks_per_sm, clip_persist_kernel, THREADS, 0);
    if (blocks_per_sm < 1) blocks_per_sm = 1;

    unsigned grid = (unsigned)(sm_count * blocks_per_sm);  // exactly one wave

    if (n % 4 == 0 && (n / 4) < (1LL << 31)) {
        unsigned n4 = (unsigned)(n / 4);
        // Don't launch more threads than vectors.
        unsigned max_blocks = (n4 + THREADS - 1) / THREADS;
        if (grid > max_blocks) grid = max_blocks;
        clip_persist_kernel<<<grid, THREADS>>>((const float4*)x, (float4*)out, n4);
        return;
    }

    // Fully scalar fallback.
    int blocks = (int)((n + THREADS - 1) / THREADS);
    if (blocks > 65535) blocks = 65535;
    clip_scalar_kernel<<<blocks, THREADS>>>(x, out, n);
}